// round 2
// baseline (speedup 1.0000x reference)
#include <cuda_runtime.h>
#include <cuda_bf16.h>

#define NUM_HEADS 16
#define TM 64
#define TN 64
#define TK 16
#define THREADS 256
#define AS_STRIDE 68   // padded: keeps float4 alignment (68%4==0), reduces STS conflicts

__device__ int d_order[4096];
__device__ int d_head_off[NUM_HEADS + 1];

// ---------------------------------------------------------------------------
// Kernel 1: bucket tokens by head. Single CTA, N=2048 so this is trivial.
// idx is int32 (JAX x64-disabled downgrades the requested int64).
// ---------------------------------------------------------------------------
__global__ void bucket_kernel(const int* __restrict__ idx, int N) {
    __shared__ int cnt[NUM_HEADS];
    __shared__ int base[NUM_HEADS];
    int t = threadIdx.x;
    if (t < NUM_HEADS) cnt[t] = 0;
    __syncthreads();
    for (int i = t; i < N; i += blockDim.x) {
        int h = idx[i] & (NUM_HEADS - 1);   // defensive mask
        atomicAdd(&cnt[h], 1);
    }
    __syncthreads();
    if (t == 0) {
        int s = 0;
        for (int h = 0; h < NUM_HEADS; h++) {
            base[h] = s;
            d_head_off[h] = s;
            s += cnt[h];
        }
        d_head_off[NUM_HEADS] = s;
    }
    __syncthreads();
    for (int i = t; i < N; i += blockDim.x) {
        int h = idx[i] & (NUM_HEADS - 1);
        int p = atomicAdd(&base[h], 1);
        d_order[p] = i;
    }
}

// ---------------------------------------------------------------------------
// Kernel 2: grouped GEMM. For head z: Y[tok, h] = X[tok,:] @ W[z,:,:] + B[z,h]
// Tile: 64(M) x 64(N) x 16(K), 256 threads, 4x4 microtile per thread.
// Grid: (H/TN, ceil(N/TM), NUM_HEADS); blocks beyond a head's token count
// exit immediately.
// ---------------------------------------------------------------------------
__global__ __launch_bounds__(THREADS) void mlin_gemm(
    const float* __restrict__ X,   // (N, D)
    const float* __restrict__ W,   // (NUM_HEADS, D, H)
    const float* __restrict__ B,   // (NUM_HEADS, H)
    float* __restrict__ Y,         // (N, H)
    int D, int H)
{
    const int head = blockIdx.z;
    const int off  = d_head_off[head];
    const int M    = d_head_off[head + 1] - off;
    const int m0   = blockIdx.y * TM;
    if (m0 >= M) return;
    const int h0   = blockIdx.x * TN;

    __shared__ float As[TK][AS_STRIDE];
    __shared__ float Bs[TK][TN];
    __shared__ int   tok_s[TM];

    const int tid = threadIdx.x;

    if (tid < TM) {
        int m = m0 + tid;
        tok_s[tid] = (m < M) ? d_order[off + m] : -1;
    }
    __syncthreads();

    // A-load mapping: 64 rows x 16 k, one float4 along k per thread
    const int a_row = tid >> 2;          // 0..63
    const int a_k0  = (tid & 3) * 4;     // 0,4,8,12
    const int a_tok = tok_s[a_row];

    // B-load mapping: 16 k-rows x 64 h, one float4 along h per thread
    const int b_k   = tid >> 4;          // 0..15
    const int b_n0  = (tid & 15) * 4;    // 0..60

    // compute mapping: 16x16 thread grid, 4x4 microtile
    const int tm0 = (tid >> 4) * 4;
    const int tn0 = (tid & 15) * 4;

    float acc[4][4];
    #pragma unroll
    for (int i = 0; i < 4; i++)
        #pragma unroll
        for (int j = 0; j < 4; j++)
            acc[i][j] = 0.0f;

    const float* wbase = W + ((size_t)head * D) * H + h0;

    for (int kt = 0; kt < D; kt += TK) {
        // load A tile (gathered token rows), transposed into As[k][m]
        float4 av = make_float4(0.f, 0.f, 0.f, 0.f);
        if (a_tok >= 0)
            av = *reinterpret_cast<const float4*>(X + (size_t)a_tok * D + kt + a_k0);
        As[a_k0 + 0][a_row] = av.x;
        As[a_k0 + 1][a_row] = av.y;
        As[a_k0 + 2][a_row] = av.z;
        As[a_k0 + 3][a_row] = av.w;

        // load B tile (contiguous in h)
        float4 bv = *reinterpret_cast<const float4*>(wbase + (size_t)(kt + b_k) * H + b_n0);
        *reinterpret_cast<float4*>(&Bs[b_k][b_n0]) = bv;

        __syncthreads();

        #pragma unroll
        for (int k = 0; k < TK; k++) {
            float a[4], b[4];
            float4 af = *reinterpret_cast<const float4*>(&As[k][tm0]);
            a[0] = af.x; a[1] = af.y; a[2] = af.z; a[3] = af.w;
            float4 bf = *reinterpret_cast<const float4*>(&Bs[k][tn0]);
            b[0] = bf.x; b[1] = bf.y; b[2] = bf.z; b[3] = bf.w;
            #pragma unroll
            for (int i = 0; i < 4; i++)
                #pragma unroll
                for (int j = 0; j < 4; j++)
                    acc[i][j] = fmaf(a[i], b[j], acc[i][j]);
        }
        __syncthreads();
    }

    // epilogue: add bias, scatter rows back to token positions
    float4 bias = *reinterpret_cast<const float4*>(B + (size_t)head * H + h0 + tn0);
    #pragma unroll
    for (int i = 0; i < 4; i++) {
        int m = tm0 + i;
        if (m0 + m < M) {
            int tok = tok_s[m];
            float4 o;
            o.x = acc[i][0] + bias.x;
            o.y = acc[i][1] + bias.y;
            o.z = acc[i][2] + bias.z;
            o.w = acc[i][3] + bias.w;
            *reinterpret_cast<float4*>(Y + (size_t)tok * H + h0 + tn0) = o;
        }
    }
}

extern "C" void kernel_launch(void* const* d_in, const int* in_sizes, int n_in,
                              void* d_out, int out_size) {
    const float* X   = (const float*)d_in[0];   // (N, D) fp32
    const int*   idx = (const int*)d_in[1];     // (N,)   int32 (JAX x64 off)
    const float* W   = (const float*)d_in[2];   // (16, D, H) fp32
    const float* B   = (const float*)d_in[3];   // (16, H) fp32
    float*       Y   = (float*)d_out;           // (N, H) fp32

    const int N = in_sizes[1];
    const int D = in_sizes[0] / N;
    const int H = in_sizes[3] / NUM_HEADS;

    bucket_kernel<<<1, 256>>>(idx, N);

    dim3 grid(H / TN, (N + TM - 1) / TM, NUM_HEADS);
    mlin_gemm<<<grid, THREADS>>>(X, W, B, Y, D, H);
}

// round 3
// speedup vs baseline: 1.3865x; 1.3865x over previous
#include <cuda_runtime.h>
#include <mma.h>
using namespace nvcuda;

#define NUM_HEADS 16
#define TM 64
#define TN 64
#define TKT 32
#define THREADS 128
#define A_LD 40     // 32 k + 8 pad  (mult of 4 floats -> 16B aligned rows)
#define B_LD 68     // 64 n + 4 pad
#define C_LD 68

__device__ int d_order[4096];
__device__ int d_head_off[NUM_HEADS + 1];

// ---------------------------------------------------------------------------
// Kernel 1: bucket tokens by head (idx is int32).
// ---------------------------------------------------------------------------
__global__ void bucket_kernel(const int* __restrict__ idx, int N) {
    __shared__ int cnt[NUM_HEADS];
    __shared__ int base[NUM_HEADS];
    int t = threadIdx.x;
    if (t < NUM_HEADS) cnt[t] = 0;
    __syncthreads();
    for (int i = t; i < N; i += blockDim.x)
        atomicAdd(&cnt[idx[i] & (NUM_HEADS - 1)], 1);
    __syncthreads();
    if (t == 0) {
        int s = 0;
        for (int h = 0; h < NUM_HEADS; h++) {
            base[h] = s;
            d_head_off[h] = s;
            s += cnt[h];
        }
        d_head_off[NUM_HEADS] = s;
    }
    __syncthreads();
    for (int i = t; i < N; i += blockDim.x) {
        int h = idx[i] & (NUM_HEADS - 1);
        int p = atomicAdd(&base[h], 1);
        d_order[p] = i;
    }
}

// ---------------------------------------------------------------------------
// Kernel 2: grouped GEMM on tf32 tensor cores.
// CTA tile 64x64, 4 warps each computing a 32x32 warp tile (2x2 m16n16k8
// fragments). K-tile 32, double-buffered smem with register prefetch:
// exactly one __syncthreads per k-tile. Epilogue stages C through smem
// (overlapping the A/B buffers) for coalesced scattered stores.
// ---------------------------------------------------------------------------
__global__ __launch_bounds__(THREADS) void mlin_wmma(
    const float* __restrict__ X,     // (N, D)
    const float* __restrict__ W,     // (NUM_HEADS, D, H)
    const float* __restrict__ Bias,  // (NUM_HEADS, H)
    float* __restrict__ Y,           // (N, H)
    int D, int H)
{
    const int head = blockIdx.z;
    const int off  = d_head_off[head];
    const int M    = d_head_off[head + 1] - off;
    const int m0   = blockIdx.y * TM;
    if (m0 >= M) return;
    const int h0   = blockIdx.x * TN;

    // Shared memory: A/B double buffers; C-staging overlaps them (used only
    // after the final mainloop barrier). Keeps static smem under 48KB.
    __shared__ __align__(16) float AsBuf[2][TM][A_LD];        // 20.0 KB
    __shared__ __align__(16) float BsBuf[2][TKT][B_LD];       // 17.0 KB
    __shared__ int tok_s[TM];
    float (*Cs)[C_LD] = reinterpret_cast<float (*)[C_LD]>(&AsBuf[0][0][0]); // 17.0 KB, overlaps

    const int tid  = threadIdx.x;
    const int wid  = tid >> 5;

    if (tid < TM) {
        int m = m0 + tid;
        tok_s[tid] = (m < M) ? d_order[off + m] : -1;
    }
    __syncthreads();

    // Global-load mappings
    const int a_row = tid >> 1;              // 0..63
    const int a_k0  = (tid & 1) * 16;        // 0 or 16
    const int b_row = tid >> 2;              // 0..31
    const int b_n0  = (tid & 3) * 16;        // 0,16,32,48

    const int a_tok = tok_s[a_row];
    const float* aptr = X + (size_t)(a_tok < 0 ? 0 : a_tok) * D;
    const bool   a_ok = (a_tok >= 0);
    const float* wptr = W + (size_t)head * D * H + h0;

    // Warp tile position
    const int wm = (wid >> 1) * 32;
    const int wn = (wid & 1) * 32;

    wmma::fragment<wmma::accumulator, 16, 16, 8, float> acc[2][2];
    #pragma unroll
    for (int i = 0; i < 2; i++)
        #pragma unroll
        for (int j = 0; j < 2; j++)
            wmma::fill_fragment(acc[i][j], 0.0f);

    float4 ar[4], br[4];

    // prologue: fetch k-tile 0
    #pragma unroll
    for (int i = 0; i < 4; i++) {
        ar[i] = a_ok ? *reinterpret_cast<const float4*>(aptr + a_k0 + i * 4)
                     : make_float4(0.f, 0.f, 0.f, 0.f);
        br[i] = *reinterpret_cast<const float4*>(wptr + (size_t)b_row * H + b_n0 + i * 4);
    }
    #pragma unroll
    for (int i = 0; i < 4; i++) {
        *reinterpret_cast<float4*>(&AsBuf[0][a_row][a_k0 + i * 4]) = ar[i];
        *reinterpret_cast<float4*>(&BsBuf[0][b_row][b_n0 + i * 4]) = br[i];
    }
    __syncthreads();

    const int NT = D / TKT;   // 16
    for (int t = 0; t < NT; t++) {
        const int buf = t & 1;

        // prefetch next k-tile into registers (overlaps with mma below)
        if (t + 1 < NT) {
            const int kt = (t + 1) * TKT;
            #pragma unroll
            for (int i = 0; i < 4; i++) {
                ar[i] = a_ok ? *reinterpret_cast<const float4*>(aptr + kt + a_k0 + i * 4)
                             : make_float4(0.f, 0.f, 0.f, 0.f);
                br[i] = *reinterpret_cast<const float4*>(wptr + (size_t)(kt + b_row) * H + b_n0 + i * 4);
            }
        }

        // consume current smem tile
        #pragma unroll
        for (int ks = 0; ks < TKT; ks += 8) {
            wmma::fragment<wmma::matrix_a, 16, 16, 8, wmma::precision::tf32, wmma::row_major> af[2];
            wmma::fragment<wmma::matrix_b, 16, 16, 8, wmma::precision::tf32, wmma::row_major> bf[2];
            #pragma unroll
            for (int i = 0; i < 2; i++) {
                wmma::load_matrix_sync(af[i], &AsBuf[buf][wm + i * 16][ks], A_LD);
                #pragma unroll
                for (int e = 0; e < af[i].num_elements; e++)
                    af[i].x[e] = wmma::__float_to_tf32(af[i].x[e]);
            }
            #pragma unroll
            for (int j = 0; j < 2; j++) {
                wmma::load_matrix_sync(bf[j], &BsBuf[buf][ks][wn + j * 16], B_LD);
                #pragma unroll
                for (int e = 0; e < bf[j].num_elements; e++)
                    bf[j].x[e] = wmma::__float_to_tf32(bf[j].x[e]);
            }
            #pragma unroll
            for (int i = 0; i < 2; i++)
                #pragma unroll
                for (int j = 0; j < 2; j++)
                    wmma::mma_sync(acc[i][j], af[i], bf[j], acc[i][j]);
        }

        // publish prefetched tile into the other buffer
        if (t + 1 < NT) {
            const int nbuf = (t + 1) & 1;
            #pragma unroll
            for (int i = 0; i < 4; i++) {
                *reinterpret_cast<float4*>(&AsBuf[nbuf][a_row][a_k0 + i * 4]) = ar[i];
                *reinterpret_cast<float4*>(&BsBuf[nbuf][b_row][b_n0 + i * 4]) = br[i];
            }
        }
        __syncthreads();
    }

    // epilogue: stage C in smem (overlapping A buffers — safe after last sync)
    #pragma unroll
    for (int i = 0; i < 2; i++)
        #pragma unroll
        for (int j = 0; j < 2; j++)
            wmma::store_matrix_sync(&Cs[wm + i * 16][wn + j * 16], acc[i][j], C_LD,
                                    wmma::mem_row_major);
    __syncthreads();

    const int c_row  = tid >> 1;
    const int c_col0 = (tid & 1) * 32;
    if (m0 + c_row < M) {
        const int tok = tok_s[c_row];
        const float* bptr = Bias + (size_t)head * H + h0 + c_col0;
        float* yptr = Y + (size_t)tok * H + h0 + c_col0;
        #pragma unroll
        for (int j = 0; j < 32; j += 4) {
            float4 c = *reinterpret_cast<const float4*>(&Cs[c_row][c_col0 + j]);
            float4 b = *reinterpret_cast<const float4*>(bptr + j);
            c.x += b.x; c.y += b.y; c.z += b.z; c.w += b.w;
            *reinterpret_cast<float4*>(yptr + j) = c;
        }
    }
}

extern "C" void kernel_launch(void* const* d_in, const int* in_sizes, int n_in,
                              void* d_out, int out_size) {
    const float* X    = (const float*)d_in[0];   // (N, D) fp32
    const int*   idx  = (const int*)d_in[1];     // (N,)   int32
    const float* W    = (const float*)d_in[2];   // (16, D, H) fp32
    const float* Bias = (const float*)d_in[3];   // (16, H) fp32
    float*       Y    = (float*)d_out;           // (N, H) fp32

    const int N = in_sizes[1];
    const int D = in_sizes[0] / N;
    const int H = in_sizes[3] / NUM_HEADS;

    bucket_kernel<<<1, 256>>>(idx, N);

    dim3 grid(H / TN, (N + TM - 1) / TM, NUM_HEADS);
    mlin_wmma<<<grid, THREADS>>>(X, W, Bias, Y, D, H);
}